// round 13
// baseline (speedup 1.0000x reference)
#include <cuda_runtime.h>
#include <cuda_bf16.h>
#include <cuda_fp16.h>
#include <cstdint>

// Problem constants
#define NN      50000        // nodes
#define EE      800000       // edges
#define MM      (EE + NN)    // edges + self loops
#define HH      8            // heads
#define RP1     9            // relations + 1 (self-loop relation = 8)
#define NEG_SLOPE 0.2f

#define NB      80           // GEMM N: 64 hidden dims + 8 s_in + 8 s_out
#define MT2     391          // ceil(NN / 128)
#define G16     3128         // 391*8 node-groups of 16
#define PREPX_B 1564         // G16*128/256

// ---------------------------------------------------------------------------
// Scratch (device globals; allocation-free per harness rules).
// Zero-init at load; g_cnt / g_total are re-zeroed every call (invariant).
// ---------------------------------------------------------------------------
__device__ __half         g_hidden[(size_t)RP1 * NN * 64]; // 57.6 MB fp16
__device__ __half         g_s[(size_t)RP1 * NN * 16];      // 14.4 MB fp16
__device__ __half         g_Bh[RP1 * NB * 64];             // B' rows fp16 (K=64)
__device__ uint4          g_xf[(size_t)G16 * 4 * 32];      // A fp16 frag order
__device__ uint4          g_Bf[RP1 * 640];                 // B fp16 frag order
// CSR scratch
__device__ int            g_cnt[NN];                       // zero-invariant (degree)
__device__ int            g_rank[MM];                      // edge's rank within dest
__device__ int            g_off[NN];                       // dynamic slice starts
__device__ int            g_total;                         // zero-invariant
__device__ uint2          g_erec[MM];                      // (bi | rel<<24, ew)

// ---------------------------------------------------------------------------
__device__ __forceinline__ void mma_f16(float* c, uint32_t a0, uint32_t a1,
                                        uint32_t a2, uint32_t a3,
                                        uint32_t b0, uint32_t b1) {
    asm volatile(
        "mma.sync.aligned.m16n8k16.row.col.f32.f16.f16.f32 "
        "{%0,%1,%2,%3}, {%4,%5,%6,%7}, {%8,%9}, {%0,%1,%2,%3};"
        : "+f"(c[0]), "+f"(c[1]), "+f"(c[2]), "+f"(c[3])
        : "r"(a0), "r"(a1), "r"(a2), "r"(a3), "r"(b0), "r"(b1));
}
__device__ __forceinline__ uint32_t pack_h2(float a, float b) {
    __half2 p = __floats2half2_rn(a, b);
    return *(uint32_t*)&p;
}

// ---------------------------------------------------------------------------
// K1: histogram + per-edge rank (atomic return value).
// ---------------------------------------------------------------------------
__global__ __launch_bounds__(256) void k_hist(const int* __restrict__ node_out) {
    int m = blockIdx.x * 256 + threadIdx.x;
    if (m >= MM) return;
    int no = (m < EE) ? node_out[m] : (m - EE);
    g_rank[m] = atomicAdd(&g_cnt[no], 1);
}

// ---------------------------------------------------------------------------
// K2: prepX || prepWB (pure-write preps, fused).
// ---------------------------------------------------------------------------
__global__ __launch_bounds__(256) void k_prep(const float* __restrict__ x,
                                              const float* __restrict__ W,
                                              const float* __restrict__ query) {
    const int bid = blockIdx.x;
    const int tid = threadIdx.x;

    if (bid < PREPX_B) {
        // ---- prepX: x -> A-fragment order fp16 (K=64) ----
        int i = bid * 256 + tid;
        const int lane = i & 31;
        const int cbb  = (i >> 5) & 3;
        const int g16  = i >> 7;
        const int g = lane >> 2, t = lane & 3;
        const int n0 = g16 * 16 + g, n1 = n0 + 8;
        const int c0 = cbb * 16 + 2 * t;

        float2 v00 = {0.f, 0.f}, v01 = {0.f, 0.f}, v10 = {0.f, 0.f}, v11 = {0.f, 0.f};
        if (n0 < NN) {
            v00 = *(const float2*)(x + (size_t)n0 * 64 + c0);
            v01 = *(const float2*)(x + (size_t)n0 * 64 + c0 + 8);
        }
        if (n1 < NN) {
            v10 = *(const float2*)(x + (size_t)n1 * 64 + c0);
            v11 = *(const float2*)(x + (size_t)n1 * 64 + c0 + 8);
        }
        uint4 a;
        a.x = pack_h2(v00.x, v00.y);
        a.y = pack_h2(v10.x, v10.y);
        a.z = pack_h2(v01.x, v01.y);
        a.w = pack_h2(v11.x, v11.y);
        g_xf[((size_t)g16 * 4 + cbb) * 32 + lane] = a;
        return;
    }

    // ---- prepWB: B' rows fp16, then permute to frag order ----
    {
        const int r = bid - PREPX_B;
        const float* Wr = W + (size_t)r * 64 * 64;

        if (tid < NB) {
            __half* b = g_Bh + ((size_t)r * NB + tid) * 64;
            for (int i = 0; i < 64; i++) {
                float v;
                if (tid < 64) {
                    v = Wr[tid * 64 + i];
                } else {
                    int h = (tid - 64) & 7;
                    int par = (tid - 64) >> 3;
                    const float* q = query + ((size_t)r * HH + h) * 16 + par;
                    float acc = 0.f;
                    #pragma unroll
                    for (int j = 0; j < 8; j++) acc += q[2 * j] * Wr[(h * 8 + j) * 64 + i];
                    v = acc;
                }
                b[i] = __float2half(v);
            }
        }
        __syncthreads();

        #pragma unroll
        for (int k = 0; k < 3; k++) {
            int f = tid + k * 256;         // 0..639
            if (f < 640) {
                int cb   = f / 160;
                int rem  = f - cb * 160;
                int j    = rem >> 5;
                int lane = rem & 31;
                int g = lane >> 2, t = lane & 3;
                const __half* B0 = g_Bh + ((size_t)r * NB + j * 16 + g) * 64;
                const __half* B1 = B0 + 8 * 64;
                uint4 v;
                v.x = *(const uint32_t*)(B0 + cb * 16 + 2 * t);
                v.y = *(const uint32_t*)(B0 + cb * 16 + 8 + 2 * t);
                v.z = *(const uint32_t*)(B1 + cb * 16 + 2 * t);
                v.w = *(const uint32_t*)(B1 + cb * 16 + 8 + 2 * t);
                g_Bf[r * 640 + f] = v;
            }
        }
    }
}

// ---------------------------------------------------------------------------
// K3: gemm — fp16 mma, K=64, frag-direct A, 2 relations per CTA.
// ---------------------------------------------------------------------------
__global__ __launch_bounds__(128) void k_gemm(int dummy) {
    __shared__ uint4 sBf[2][640];          // 20 KB

    const int r0    = blockIdx.y * 2;
    const int nrel  = (r0 + 1 < RP1) ? 2 : 1;
    const int mbase = blockIdx.x * 128;
    const int tid   = threadIdx.x;
    const int w     = tid >> 5, lane = tid & 31;

    for (int p = 0; p < nrel; p++)
        #pragma unroll
        for (int k = 0; k < 5; k++)
            sBf[p][tid + k * 128] = g_Bf[(r0 + p) * 640 + tid + k * 128];

    uint4 af[2][4];
    const int gb = blockIdx.x * 8 + w * 2;
    #pragma unroll
    for (int i = 0; i < 2; i++)
        #pragma unroll
        for (int cb = 0; cb < 4; cb++)
            af[i][cb] = g_xf[((size_t)(gb + i) * 4 + cb) * 32 + lane];

    __syncthreads();

    const int g = lane >> 2, t = lane & 3;

    for (int p = 0; p < nrel; p++) {
        const int r = r0 + p;

        float acc[2][40];
        #pragma unroll
        for (int i = 0; i < 2; i++)
            #pragma unroll
            for (int k = 0; k < 40; k++) acc[i][k] = 0.f;

        #pragma unroll
        for (int cb = 0; cb < 4; cb++) {
            uint4 bf[5];
            #pragma unroll
            for (int j = 0; j < 5; j++) bf[j] = sBf[p][(cb * 5 + j) * 32 + lane];

            #pragma unroll
            for (int i = 0; i < 2; i++)
                #pragma unroll
                for (int nt = 0; nt < 10; nt++) {
                    uint32_t b0 = (nt & 1) ? bf[nt >> 1].z : bf[nt >> 1].x;
                    uint32_t b1 = (nt & 1) ? bf[nt >> 1].w : bf[nt >> 1].y;
                    mma_f16(acc[i] + nt * 4, af[i][cb].x, af[i][cb].y,
                            af[i][cb].z, af[i][cb].w, b0, b1);
                }
        }

        #pragma unroll
        for (int i = 0; i < 2; i++)
            #pragma unroll
            for (int half = 0; half < 2; half++) {
                int n = mbase + w * 32 + i * 16 + g + 8 * half;
                if (n < NN) {
                    uint32_t* hd = (uint32_t*)(g_hidden + ((size_t)r * NN + n) * 64 + 2 * t);
                    #pragma unroll
                    for (int nt = 0; nt < 8; nt++)
                        hd[nt * 4] = pack_h2(acc[i][nt * 4 + 2 * half],
                                             acc[i][nt * 4 + 2 * half + 1]);
                    uint32_t* sd = (uint32_t*)(g_s + ((size_t)r * NN + n) * 16 + 2 * t);
                    #pragma unroll
                    for (int nt = 8; nt < 10; nt++)
                        sd[(nt - 8) * 4] = pack_h2(acc[i][nt * 4 + 2 * half],
                                                   acc[i][nt * 4 + 2 * half + 1]);
                }
            }
    }
}

// ---------------------------------------------------------------------------
// K4: dynamic slice allocation — replaces the whole prefix-sum chain.
//   Slices are contiguous but unordered; grouping is all k_agg needs.
// ---------------------------------------------------------------------------
__global__ void k_alloc() {
    int i = blockIdx.x * 256 + threadIdx.x;
    if (i < NN) g_off[i] = atomicAdd(&g_total, g_cnt[i]);
}

// ---------------------------------------------------------------------------
// K5: scatter into CSR slices — no atomics (rank precomputed).
// ---------------------------------------------------------------------------
__global__ __launch_bounds__(256) void k_scatter(const int*   __restrict__ node_in,
                                                 const int*   __restrict__ node_out,
                                                 const int*   __restrict__ relation,
                                                 const float* __restrict__ edge_weight) {
    int m = blockIdx.x * 256 + threadIdx.x;
    if (m >= MM) return;
    int ni, no, r; float ew;
    if (m < EE) {
        ni = node_in[m]; no = node_out[m]; r = relation[m]; ew = edge_weight[m];
    } else {
        ni = no = m - EE; r = RP1 - 1; ew = 1.f;
    }
    int pos = g_off[no] + g_rank[m];
    uint32_t bi = (uint32_t)r * NN + (uint32_t)ni;
    g_erec[pos] = make_uint2(bi | ((uint32_t)r << 24), __float_as_uint(ew));
}

// ---------------------------------------------------------------------------
// K6: gather-side aggregation, 4 edges per warp-step.
//   Restores g_cnt / g_total zero-invariants.
// ---------------------------------------------------------------------------
__global__ __launch_bounds__(256) void k_agg(float* __restrict__ out) {
    if (blockIdx.x == 0 && threadIdx.x == 0) g_total = 0;   // restore invariant
    const int n = blockIdx.x * 8 + (threadIdx.x >> 5);
    if (n >= NN) return;
    const int lane = threadIdx.x & 31;
    const int jj = lane >> 3, dd = lane & 7;

    const int start = g_off[n];
    const int deg   = g_cnt[n];
    const int end   = start + deg;
    if (lane == 0) g_cnt[n] = 0;           // restore invariant

    float acc[8];
    #pragma unroll
    for (int k = 0; k < 8; k++) acc[k] = 0.f;
    float esum = 0.f;

    for (int e = start; e < end; e += 4) {
        const int idx = e + jj;
        uint2 cur = (idx < end) ? g_erec[idx] : make_uint2(0u, 0u);
        const uint32_t bi = cur.x & 0xFFFFFFu;
        const uint32_t r  = cur.x >> 24;

        const uint4 hv = *(const uint4*)(g_hidden + (size_t)bi * 64 + dd * 8);
        const float si = __half2float(g_s[(size_t)bi * 16 + dd]);
        const float so = __half2float(g_s[((size_t)r * NN + n) * 16 + 8 + dd]);

        float w = si + so;
        w = (w > 0.f) ? w : NEG_SLOPE * w;
        const float ee = __expf(w) * __uint_as_float(cur.y);

        const float2 f0 = __half22float2(*(const __half2*)&hv.x);
        const float2 f1 = __half22float2(*(const __half2*)&hv.y);
        const float2 f2 = __half22float2(*(const __half2*)&hv.z);
        const float2 f3 = __half22float2(*(const __half2*)&hv.w);
        acc[0] += ee * f0.x; acc[1] += ee * f0.y;
        acc[2] += ee * f1.x; acc[3] += ee * f1.y;
        acc[4] += ee * f2.x; acc[5] += ee * f2.y;
        acc[6] += ee * f3.x; acc[7] += ee * f3.y;
        esum += ee;
    }

    #pragma unroll
    for (int o = 8; o <= 16; o <<= 1) {
        #pragma unroll
        for (int k = 0; k < 8; k++)
            acc[k] += __shfl_xor_sync(0xffffffffu, acc[k], o);
        esum += __shfl_xor_sync(0xffffffffu, esum, o);
    }

    if (jj == 0) {
        const float inv = 1.f / esum;      // >=1 edge per node (self-loop)
        float4 o0, o1;
        o0.x = fmaxf(acc[0] * inv, 0.f);
        o0.y = fmaxf(acc[1] * inv, 0.f);
        o0.z = fmaxf(acc[2] * inv, 0.f);
        o0.w = fmaxf(acc[3] * inv, 0.f);
        o1.x = fmaxf(acc[4] * inv, 0.f);
        o1.y = fmaxf(acc[5] * inv, 0.f);
        o1.z = fmaxf(acc[6] * inv, 0.f);
        o1.w = fmaxf(acc[7] * inv, 0.f);
        *(float4*)(out + (size_t)n * 64 + dd * 8)     = o0;
        *(float4*)(out + (size_t)n * 64 + dd * 8 + 4) = o1;
    }
}

// ---------------------------------------------------------------------------
extern "C" void kernel_launch(void* const* d_in, const int* in_sizes, int n_in,
                              void* d_out, int out_size) {
    const float* x           = (const float*)d_in[0];
    const float* W_tau       = (const float*)d_in[1];
    const float* query       = (const float*)d_in[2];
    const int*   node_in     = (const int*)  d_in[3];
    const int*   node_out    = (const int*)  d_in[4];
    const int*   relation    = (const int*)  d_in[5];
    const float* edge_weight = (const float*)d_in[6];

    // 1: degree histogram + edge ranks
    k_hist<<<(MM + 255) / 256, 256>>>(node_out);
    // 2: prepX || prepWB
    k_prep<<<PREPX_B + RP1, 256>>>(x, W_tau, query);
    // 3: node transform (tensor cores)
    dim3 gg(MT2, 5);
    k_gemm<<<gg, 128>>>(0);
    // 4: dynamic slice allocation (replaces 3-kernel scan)
    k_alloc<<<(NN + 255) / 256, 256>>>();
    // 5: atomic-free scatter
    k_scatter<<<(MM + 255) / 256, 256>>>(node_in, node_out, relation, edge_weight);
    // 6: gather-side aggregation (-s 5 -c 1 profiles this)
    k_agg<<<(NN + 7) / 8, 256>>>((float*)d_out);
}

// round 14
// speedup vs baseline: 1.5667x; 1.5667x over previous
#include <cuda_runtime.h>
#include <cuda_bf16.h>
#include <cuda_fp16.h>
#include <cstdint>

// Problem constants
#define NN      50000        // nodes
#define EE      800000       // edges
#define MM      (EE + NN)    // edges + self loops
#define HH      8            // heads
#define RP1     9            // relations + 1 (self-loop relation = 8)
#define NEG_SLOPE 0.2f

#define NB      80           // GEMM N: 64 hidden dims + 8 s_in + 8 s_out
#define MT2     391          // ceil(NN / 128)
#define G16     3128         // 391*8 node-groups of 16
#define SB1     196          // ceil(NN / 256) scan blocks

// front-kernel block ranges (256 threads each)
#define HIST_B   3321        // ceil(MM/256)
#define PREPX_B  1564        // G16*128/256
#define FRONT_B  (HIST_B + PREPX_B + RP1)

// ---------------------------------------------------------------------------
// Scratch (device globals; allocation-free per harness rules).
// Zero-init at load; g_cnt / g_cnt2 re-zeroed every call (invariants).
// ---------------------------------------------------------------------------
__device__ __half         g_hidden[(size_t)RP1 * NN * 64]; // 57.6 MB fp16
__device__ __half         g_s[(size_t)RP1 * NN * 16];      // 14.4 MB fp16
__device__ __half         g_Bh[RP1 * NB * 64];             // B' rows fp16 (K=64)
__device__ uint4          g_xf[(size_t)G16 * 4 * 32];      // A fp16 frag order
__device__ uint4          g_Bf[RP1 * 640];                 // B fp16 frag order
// CSR sort scratch
__device__ int            g_cnt[NN];                       // zero-invariant
__device__ int            g_cnt2[NN];                      // zero-invariant
__device__ int            g_off[NN + 1];
__device__ int            g_bsum[256];
__device__ uint2          g_erec[MM];                      // (bi | rel<<24, ew)

// ---------------------------------------------------------------------------
__device__ __forceinline__ void mma_f16(float* c, uint32_t a0, uint32_t a1,
                                        uint32_t a2, uint32_t a3,
                                        uint32_t b0, uint32_t b1) {
    asm volatile(
        "mma.sync.aligned.m16n8k16.row.col.f32.f16.f16.f32 "
        "{%0,%1,%2,%3}, {%4,%5,%6,%7}, {%8,%9}, {%0,%1,%2,%3};"
        : "+f"(c[0]), "+f"(c[1]), "+f"(c[2]), "+f"(c[3])
        : "r"(a0), "r"(a1), "r"(a2), "r"(a3), "r"(b0), "r"(b1));
}
__device__ __forceinline__ uint32_t pack_h2(float a, float b) {
    __half2 p = __floats2half2_rn(a, b);
    return *(uint32_t*)&p;
}

// ---------------------------------------------------------------------------
// K_front: hist || prepX || prepWB (independent tasks, no smem in any branch).
//   hist uses fire-and-forget atomicAdd (REDG path — no return value).
// ---------------------------------------------------------------------------
__global__ __launch_bounds__(256) void k_front(const float* __restrict__ x,
                                               const float* __restrict__ W,
                                               const float* __restrict__ query,
                                               const int*   __restrict__ node_out) {
    const int bid = blockIdx.x;
    const int tid = threadIdx.x;

    if (bid < HIST_B) {
        int m = bid * 256 + tid;
        if (m < MM) {
            int no = (m < EE) ? node_out[m] : (m - EE);
            atomicAdd(&g_cnt[no], 1);
        }
        return;
    }

    if (bid < HIST_B + PREPX_B) {
        // ---- prepX: x -> A-fragment order fp16 (K=64) ----
        int i = (bid - HIST_B) * 256 + tid;
        const int lane = i & 31;
        const int cbb  = (i >> 5) & 3;
        const int g16  = i >> 7;
        const int g = lane >> 2, t = lane & 3;
        const int n0 = g16 * 16 + g, n1 = n0 + 8;
        const int c0 = cbb * 16 + 2 * t;

        float2 v00 = {0.f, 0.f}, v01 = {0.f, 0.f}, v10 = {0.f, 0.f}, v11 = {0.f, 0.f};
        if (n0 < NN) {
            v00 = *(const float2*)(x + (size_t)n0 * 64 + c0);
            v01 = *(const float2*)(x + (size_t)n0 * 64 + c0 + 8);
        }
        if (n1 < NN) {
            v10 = *(const float2*)(x + (size_t)n1 * 64 + c0);
            v11 = *(const float2*)(x + (size_t)n1 * 64 + c0 + 8);
        }
        uint4 a;
        a.x = pack_h2(v00.x, v00.y);
        a.y = pack_h2(v10.x, v10.y);
        a.z = pack_h2(v01.x, v01.y);
        a.w = pack_h2(v11.x, v11.y);
        g_xf[((size_t)g16 * 4 + cbb) * 32 + lane] = a;
        return;
    }

    // ---- prepWB: B' rows fp16, then permute to frag order ----
    {
        const int r = bid - (HIST_B + PREPX_B);
        const float* Wr = W + (size_t)r * 64 * 64;

        if (tid < NB) {
            __half* b = g_Bh + ((size_t)r * NB + tid) * 64;
            for (int i = 0; i < 64; i++) {
                float v;
                if (tid < 64) {
                    v = Wr[tid * 64 + i];
                } else {
                    int h = (tid - 64) & 7;
                    int par = (tid - 64) >> 3;
                    const float* q = query + ((size_t)r * HH + h) * 16 + par;
                    float acc = 0.f;
                    #pragma unroll
                    for (int j = 0; j < 8; j++) acc += q[2 * j] * Wr[(h * 8 + j) * 64 + i];
                    v = acc;
                }
                b[i] = __float2half(v);
            }
        }
        __syncthreads();

        #pragma unroll
        for (int k = 0; k < 3; k++) {
            int f = tid + k * 256;         // 0..639
            if (f < 640) {
                int cb   = f / 160;
                int rem  = f - cb * 160;
                int j    = rem >> 5;
                int lane = rem & 31;
                int g = lane >> 2, t = lane & 3;
                const __half* B0 = g_Bh + ((size_t)r * NB + j * 16 + g) * 64;
                const __half* B1 = B0 + 8 * 64;
                uint4 v;
                v.x = *(const uint32_t*)(B0 + cb * 16 + 2 * t);
                v.y = *(const uint32_t*)(B0 + cb * 16 + 8 + 2 * t);
                v.z = *(const uint32_t*)(B1 + cb * 16 + 2 * t);
                v.w = *(const uint32_t*)(B1 + cb * 16 + 8 + 2 * t);
                g_Bf[r * 640 + f] = v;
            }
        }
    }
}

// ---------------------------------------------------------------------------
// Scan chain (3 kernels). scan1 reads + re-zeroes g_cnt (invariant).
// ---------------------------------------------------------------------------
__device__ __forceinline__ int block_incl_scan(int v, int* wt) {
    int lane = threadIdx.x & 31, w = threadIdx.x >> 5;
    #pragma unroll
    for (int o = 1; o < 32; o <<= 1) {
        int y = __shfl_up_sync(0xffffffffu, v, o);
        if (lane >= o) v += y;
    }
    if (lane == 31) wt[w] = v;
    __syncthreads();
    if (w == 0) {
        int x = (lane < 8) ? wt[lane] : 0;
        #pragma unroll
        for (int o = 1; o < 8; o <<= 1) {
            int y = __shfl_up_sync(0xffffffffu, x, o);
            if (lane >= o) x += y;
        }
        if (lane < 8) wt[lane] = x;
    }
    __syncthreads();
    return v + ((w > 0) ? wt[w - 1] : 0);
}

__global__ void k_scan1() {
    __shared__ int wt[8];
    int i = blockIdx.x * 256 + threadIdx.x;
    int v0 = 0;
    if (i < NN) { v0 = g_cnt[i]; g_cnt[i] = 0; }   // read + restore invariant
    int incl = block_incl_scan(v0, wt);
    if (i < NN) g_off[i] = incl - v0;
    if (threadIdx.x == 255) g_bsum[blockIdx.x] = incl;
}

__global__ void k_scan2() {
    __shared__ int wt[8];
    int i = threadIdx.x;
    int v0 = (i < SB1) ? g_bsum[i] : 0;
    int incl = block_incl_scan(v0, wt);
    g_bsum[i] = incl - v0;
}

__global__ void k_scan3() {
    int i = blockIdx.x * 256 + threadIdx.x;
    if (i < NN) g_off[i] += g_bsum[i >> 8];
    if (i == 0) g_off[NN] = MM;
}

// ---------------------------------------------------------------------------
// Kg: gemm — fp16 mma, K=64, frag-direct A, 2 relations per CTA.
// ---------------------------------------------------------------------------
__global__ __launch_bounds__(128) void k_gemm(int dummy) {
    __shared__ uint4 sBf[2][640];          // 20 KB

    const int r0    = blockIdx.y * 2;
    const int nrel  = (r0 + 1 < RP1) ? 2 : 1;
    const int mbase = blockIdx.x * 128;
    const int tid   = threadIdx.x;
    const int w     = tid >> 5, lane = tid & 31;

    for (int p = 0; p < nrel; p++)
        #pragma unroll
        for (int k = 0; k < 5; k++)
            sBf[p][tid + k * 128] = g_Bf[(r0 + p) * 640 + tid + k * 128];

    uint4 af[2][4];
    const int gb = blockIdx.x * 8 + w * 2;
    #pragma unroll
    for (int i = 0; i < 2; i++)
        #pragma unroll
        for (int cb = 0; cb < 4; cb++)
            af[i][cb] = g_xf[((size_t)(gb + i) * 4 + cb) * 32 + lane];

    __syncthreads();

    const int g = lane >> 2, t = lane & 3;

    for (int p = 0; p < nrel; p++) {
        const int r = r0 + p;

        float acc[2][40];
        #pragma unroll
        for (int i = 0; i < 2; i++)
            #pragma unroll
            for (int k = 0; k < 40; k++) acc[i][k] = 0.f;

        #pragma unroll
        for (int cb = 0; cb < 4; cb++) {
            uint4 bf[5];
            #pragma unroll
            for (int j = 0; j < 5; j++) bf[j] = sBf[p][(cb * 5 + j) * 32 + lane];

            #pragma unroll
            for (int i = 0; i < 2; i++)
                #pragma unroll
                for (int nt = 0; nt < 10; nt++) {
                    uint32_t b0 = (nt & 1) ? bf[nt >> 1].z : bf[nt >> 1].x;
                    uint32_t b1 = (nt & 1) ? bf[nt >> 1].w : bf[nt >> 1].y;
                    mma_f16(acc[i] + nt * 4, af[i][cb].x, af[i][cb].y,
                            af[i][cb].z, af[i][cb].w, b0, b1);
                }
        }

        #pragma unroll
        for (int i = 0; i < 2; i++)
            #pragma unroll
            for (int half = 0; half < 2; half++) {
                int n = mbase + w * 32 + i * 16 + g + 8 * half;
                if (n < NN) {
                    uint32_t* hd = (uint32_t*)(g_hidden + ((size_t)r * NN + n) * 64 + 2 * t);
                    #pragma unroll
                    for (int nt = 0; nt < 8; nt++)
                        hd[nt * 4] = pack_h2(acc[i][nt * 4 + 2 * half],
                                             acc[i][nt * 4 + 2 * half + 1]);
                    uint32_t* sd = (uint32_t*)(g_s + ((size_t)r * NN + n) * 16 + 2 * t);
                    #pragma unroll
                    for (int nt = 8; nt < 10; nt++)
                        sd[(nt - 8) * 4] = pack_h2(acc[i][nt * 4 + 2 * half],
                                                   acc[i][nt * 4 + 2 * half + 1]);
                }
            }
    }
}

// ---------------------------------------------------------------------------
// K_scatter: scatter into CSR (per-node atomic rank, R11 body).
// ---------------------------------------------------------------------------
__global__ __launch_bounds__(256) void k_scatter(const int*   __restrict__ node_in,
                                                 const int*   __restrict__ node_out,
                                                 const int*   __restrict__ relation,
                                                 const float* __restrict__ edge_weight) {
    int m = blockIdx.x * 256 + threadIdx.x;
    if (m >= MM) return;
    int ni, no, r; float ew;
    if (m < EE) {
        ni = node_in[m]; no = node_out[m]; r = relation[m]; ew = edge_weight[m];
    } else {
        ni = no = m - EE; r = RP1 - 1; ew = 1.f;
    }
    int pos = g_off[no] + atomicAdd(&g_cnt2[no], 1);
    uint32_t bi = (uint32_t)r * NN + (uint32_t)ni;
    g_erec[pos] = make_uint2(bi | ((uint32_t)r << 24), __float_as_uint(ew));
}

// ---------------------------------------------------------------------------
// Ka: gather-side aggregation, 4 edges per warp-step (R11 body).
//   Restores the g_cnt2 zero-invariant.
// ---------------------------------------------------------------------------
__global__ __launch_bounds__(256) void k_agg(float* __restrict__ out) {
    const int n = blockIdx.x * 8 + (threadIdx.x >> 5);
    if (n >= NN) return;
    const int lane = threadIdx.x & 31;
    const int jj = lane >> 3, dd = lane & 7;

    const int start = g_off[n];
    const int end   = g_off[n + 1];
    if (lane == 0) g_cnt2[n] = 0;          // restore zero-invariant

    float acc[8];
    #pragma unroll
    for (int k = 0; k < 8; k++) acc[k] = 0.f;
    float esum = 0.f;

    for (int e = start; e < end; e += 4) {
        const int idx = e + jj;
        uint2 cur = (idx < end) ? g_erec[idx] : make_uint2(0u, 0u);
        const uint32_t bi = cur.x & 0xFFFFFFu;
        const uint32_t r  = cur.x >> 24;

        const uint4 hv = *(const uint4*)(g_hidden + (size_t)bi * 64 + dd * 8);
        const float si = __half2float(g_s[(size_t)bi * 16 + dd]);
        const float so = __half2float(g_s[((size_t)r * NN + n) * 16 + 8 + dd]);

        float w = si + so;
        w = (w > 0.f) ? w : NEG_SLOPE * w;
        const float ee = __expf(w) * __uint_as_float(cur.y);

        const float2 f0 = __half22float2(*(const __half2*)&hv.x);
        const float2 f1 = __half22float2(*(const __half2*)&hv.y);
        const float2 f2 = __half22float2(*(const __half2*)&hv.z);
        const float2 f3 = __half22float2(*(const __half2*)&hv.w);
        acc[0] += ee * f0.x; acc[1] += ee * f0.y;
        acc[2] += ee * f1.x; acc[3] += ee * f1.y;
        acc[4] += ee * f2.x; acc[5] += ee * f2.y;
        acc[6] += ee * f3.x; acc[7] += ee * f3.y;
        esum += ee;
    }

    #pragma unroll
    for (int o = 8; o <= 16; o <<= 1) {
        #pragma unroll
        for (int k = 0; k < 8; k++)
            acc[k] += __shfl_xor_sync(0xffffffffu, acc[k], o);
        esum += __shfl_xor_sync(0xffffffffu, esum, o);
    }

    if (jj == 0) {
        const float inv = 1.f / esum;      // >=1 edge per node (self-loop)
        float4 o0, o1;
        o0.x = fmaxf(acc[0] * inv, 0.f);
        o0.y = fmaxf(acc[1] * inv, 0.f);
        o0.z = fmaxf(acc[2] * inv, 0.f);
        o0.w = fmaxf(acc[3] * inv, 0.f);
        o1.x = fmaxf(acc[4] * inv, 0.f);
        o1.y = fmaxf(acc[5] * inv, 0.f);
        o1.z = fmaxf(acc[6] * inv, 0.f);
        o1.w = fmaxf(acc[7] * inv, 0.f);
        *(float4*)(out + (size_t)n * 64 + dd * 8)     = o0;
        *(float4*)(out + (size_t)n * 64 + dd * 8 + 4) = o1;
    }
}

// ---------------------------------------------------------------------------
extern "C" void kernel_launch(void* const* d_in, const int* in_sizes, int n_in,
                              void* d_out, int out_size) {
    const float* x           = (const float*)d_in[0];
    const float* W_tau       = (const float*)d_in[1];
    const float* query       = (const float*)d_in[2];
    const int*   node_in     = (const int*)  d_in[3];
    const int*   node_out    = (const int*)  d_in[4];
    const int*   relation    = (const int*)  d_in[5];
    const float* edge_weight = (const float*)d_in[6];

    // 1: hist || prepX || prepWB
    k_front<<<FRONT_B, 256>>>(x, W_tau, query, node_out);
    // 2-4: prefix-sum offsets (g_cnt re-zeroed in scan1)
    k_scan1<<<SB1, 256>>>();
    k_scan2<<<1, 256>>>();
    k_scan3<<<SB1, 256>>>();
    // 5: node transform (tensor cores)
    dim3 gg(MT2, 5);
    k_gemm<<<gg, 128>>>(0);
    // 6: scatter into CSR
    k_scatter<<<(MM + 255) / 256, 256>>>(node_in, node_out, relation, edge_weight);
    // 7: gather-side aggregation
    k_agg<<<(NN + 7) / 8, 256>>>((float*)d_out);
}

// round 15
// speedup vs baseline: 1.6140x; 1.0302x over previous
#include <cuda_runtime.h>
#include <cuda_bf16.h>
#include <cuda_fp16.h>
#include <cstdint>

// Problem constants
#define NN      50000        // nodes
#define EE      800000       // edges
#define MM      (EE + NN)    // edges + self loops
#define HH      8            // heads
#define RP1     9            // relations + 1 (self-loop relation = 8)
#define NEG_SLOPE 0.2f

#define NB      80           // GEMM N: 64 hidden dims + 8 s_in + 8 s_out
#define MT2     391          // ceil(NN / 128)
#define G16     3128         // 391*8 node-groups of 16
#define SB1     196          // ceil(NN / 256) scan blocks
#define PREPX_B 1564         // G16*128/256

// ---------------------------------------------------------------------------
// Scratch (device globals; allocation-free per harness rules).
// Zero-init at load; g_cnt / g_cnt2 / g_done re-zeroed every call (invariants).
// ---------------------------------------------------------------------------
__device__ __half         g_hidden[(size_t)RP1 * NN * 64]; // 57.6 MB fp16
__device__ __half         g_s[(size_t)RP1 * NN * 16];      // 14.4 MB fp16
__device__ __half         g_Bh[RP1 * NB * 64];             // B' rows fp16 (K=64)
__device__ uint4          g_xf[(size_t)G16 * 4 * 32];      // A fp16 frag order
__device__ uint4          g_Bf[RP1 * 640];                 // B fp16 frag order
// CSR sort scratch
__device__ int            g_cnt[NN];                       // zero-invariant
__device__ int            g_cnt2[NN];                      // zero-invariant
__device__ int            g_off[NN + 1];                   // block-local exclusive
__device__ int            g_bsum[256];                     // block offsets (excl)
__device__ int            g_done;                          // zero-invariant
__device__ uint2          g_erec[MM];                      // (bi | rel<<24, ew)

// ---------------------------------------------------------------------------
__device__ __forceinline__ void mma_f16(float* c, uint32_t a0, uint32_t a1,
                                        uint32_t a2, uint32_t a3,
                                        uint32_t b0, uint32_t b1) {
    asm volatile(
        "mma.sync.aligned.m16n8k16.row.col.f32.f16.f16.f32 "
        "{%0,%1,%2,%3}, {%4,%5,%6,%7}, {%8,%9}, {%0,%1,%2,%3};"
        : "+f"(c[0]), "+f"(c[1]), "+f"(c[2]), "+f"(c[3])
        : "r"(a0), "r"(a1), "r"(a2), "r"(a3), "r"(b0), "r"(b1));
}
__device__ __forceinline__ uint32_t pack_h2(float a, float b) {
    __half2 p = __floats2half2_rn(a, b);
    return *(uint32_t*)&p;
}

// ---------------------------------------------------------------------------
// K1: histogram of destinations (fire-and-forget REDG atomics, 16 regs).
// ---------------------------------------------------------------------------
__global__ __launch_bounds__(256) void k_hist(const int* __restrict__ node_out) {
    int m = blockIdx.x * 256 + threadIdx.x;
    if (m >= MM) return;
    int no = (m < EE) ? node_out[m] : (m - EE);
    atomicAdd(&g_cnt[no], 1);
}

// ---------------------------------------------------------------------------
// K2: prepX — x -> A-fragment order fp16 (K=64).
// ---------------------------------------------------------------------------
__global__ __launch_bounds__(256) void k_prepX(const float* __restrict__ x) {
    int i = blockIdx.x * 256 + threadIdx.x;
    if (i >= G16 * 4 * 32) return;
    const int lane = i & 31;
    const int cbb  = (i >> 5) & 3;
    const int g16  = i >> 7;
    const int g = lane >> 2, t = lane & 3;
    const int n0 = g16 * 16 + g, n1 = n0 + 8;
    const int c0 = cbb * 16 + 2 * t;

    float2 v00 = {0.f, 0.f}, v01 = {0.f, 0.f}, v10 = {0.f, 0.f}, v11 = {0.f, 0.f};
    if (n0 < NN) {
        v00 = *(const float2*)(x + (size_t)n0 * 64 + c0);
        v01 = *(const float2*)(x + (size_t)n0 * 64 + c0 + 8);
    }
    if (n1 < NN) {
        v10 = *(const float2*)(x + (size_t)n1 * 64 + c0);
        v11 = *(const float2*)(x + (size_t)n1 * 64 + c0 + 8);
    }
    uint4 a;
    a.x = pack_h2(v00.x, v00.y);
    a.y = pack_h2(v10.x, v10.y);
    a.z = pack_h2(v01.x, v01.y);
    a.w = pack_h2(v11.x, v11.y);
    g_xf[((size_t)g16 * 4 + cbb) * 32 + lane] = a;
}

// ---------------------------------------------------------------------------
// K3: prepWB — B' rows fp16, then permute to frag order.
// ---------------------------------------------------------------------------
__global__ __launch_bounds__(256) void k_prepWB(const float* __restrict__ W,
                                                const float* __restrict__ query) {
    const int r = blockIdx.x, tid = threadIdx.x;
    const float* Wr = W + (size_t)r * 64 * 64;

    if (tid < NB) {
        __half* b = g_Bh + ((size_t)r * NB + tid) * 64;
        for (int i = 0; i < 64; i++) {
            float v;
            if (tid < 64) {
                v = Wr[tid * 64 + i];
            } else {
                int h = (tid - 64) & 7;
                int par = (tid - 64) >> 3;
                const float* q = query + ((size_t)r * HH + h) * 16 + par;
                float acc = 0.f;
                #pragma unroll
                for (int j = 0; j < 8; j++) acc += q[2 * j] * Wr[(h * 8 + j) * 64 + i];
                v = acc;
            }
            b[i] = __float2half(v);
        }
    }
    __syncthreads();

    #pragma unroll
    for (int k = 0; k < 3; k++) {
        int f = tid + k * 256;             // 0..639
        if (f < 640) {
            int cb   = f / 160;
            int rem  = f - cb * 160;
            int j    = rem >> 5;
            int lane = rem & 31;
            int g = lane >> 2, t = lane & 3;
            const __half* B0 = g_Bh + ((size_t)r * NB + j * 16 + g) * 64;
            const __half* B1 = B0 + 8 * 64;
            uint4 v;
            v.x = *(const uint32_t*)(B0 + cb * 16 + 2 * t);
            v.y = *(const uint32_t*)(B0 + cb * 16 + 8 + 2 * t);
            v.z = *(const uint32_t*)(B1 + cb * 16 + 2 * t);
            v.w = *(const uint32_t*)(B1 + cb * 16 + 8 + 2 * t);
            g_Bf[r * 640 + f] = v;
        }
    }
}

// ---------------------------------------------------------------------------
// K4: gemm — fp16 mma, K=64, frag-direct A, 2 relations per CTA (R11 body).
// ---------------------------------------------------------------------------
__global__ __launch_bounds__(128) void k_gemm(int dummy) {
    __shared__ uint4 sBf[2][640];          // 20 KB

    const int r0    = blockIdx.y * 2;
    const int nrel  = (r0 + 1 < RP1) ? 2 : 1;
    const int mbase = blockIdx.x * 128;
    const int tid   = threadIdx.x;
    const int w     = tid >> 5, lane = tid & 31;

    for (int p = 0; p < nrel; p++)
        #pragma unroll
        for (int k = 0; k < 5; k++)
            sBf[p][tid + k * 128] = g_Bf[(r0 + p) * 640 + tid + k * 128];

    uint4 af[2][4];
    const int gb = blockIdx.x * 8 + w * 2;
    #pragma unroll
    for (int i = 0; i < 2; i++)
        #pragma unroll
        for (int cb = 0; cb < 4; cb++)
            af[i][cb] = g_xf[((size_t)(gb + i) * 4 + cb) * 32 + lane];

    __syncthreads();

    const int g = lane >> 2, t = lane & 3;

    for (int p = 0; p < nrel; p++) {
        const int r = r0 + p;

        float acc[2][40];
        #pragma unroll
        for (int i = 0; i < 2; i++)
            #pragma unroll
            for (int k = 0; k < 40; k++) acc[i][k] = 0.f;

        #pragma unroll
        for (int cb = 0; cb < 4; cb++) {
            uint4 bf[5];
            #pragma unroll
            for (int j = 0; j < 5; j++) bf[j] = sBf[p][(cb * 5 + j) * 32 + lane];

            #pragma unroll
            for (int i = 0; i < 2; i++)
                #pragma unroll
                for (int nt = 0; nt < 10; nt++) {
                    uint32_t b0 = (nt & 1) ? bf[nt >> 1].z : bf[nt >> 1].x;
                    uint32_t b1 = (nt & 1) ? bf[nt >> 1].w : bf[nt >> 1].y;
                    mma_f16(acc[i] + nt * 4, af[i][cb].x, af[i][cb].y,
                            af[i][cb].z, af[i][cb].w, b0, b1);
                }
        }

        #pragma unroll
        for (int i = 0; i < 2; i++)
            #pragma unroll
            for (int half = 0; half < 2; half++) {
                int n = mbase + w * 32 + i * 16 + g + 8 * half;
                if (n < NN) {
                    uint32_t* hd = (uint32_t*)(g_hidden + ((size_t)r * NN + n) * 64 + 2 * t);
                    #pragma unroll
                    for (int nt = 0; nt < 8; nt++)
                        hd[nt * 4] = pack_h2(acc[i][nt * 4 + 2 * half],
                                             acc[i][nt * 4 + 2 * half + 1]);
                    uint32_t* sd = (uint32_t*)(g_s + ((size_t)r * NN + n) * 16 + 2 * t);
                    #pragma unroll
                    for (int nt = 8; nt < 10; nt++)
                        sd[(nt - 8) * 4] = pack_h2(acc[i][nt * 4 + 2 * half],
                                                   acc[i][nt * 4 + 2 * half + 1]);
                }
            }
    }
}

// ---------------------------------------------------------------------------
// K5: single-kernel prefix sum (last-block pattern). Replaces scan1/2/3.
//   g_off[i] = block-local exclusive; last block turns g_bsum into exclusive
//   block offsets. Consumers add g_bsum[i>>8]. Restores g_cnt / g_done.
// ---------------------------------------------------------------------------
__device__ __forceinline__ int block_incl_scan(int v, int* wt) {
    int lane = threadIdx.x & 31, w = threadIdx.x >> 5;
    #pragma unroll
    for (int o = 1; o < 32; o <<= 1) {
        int y = __shfl_up_sync(0xffffffffu, v, o);
        if (lane >= o) v += y;
    }
    if (lane == 31) wt[w] = v;
    __syncthreads();
    if (w == 0) {
        int x = (lane < 8) ? wt[lane] : 0;
        #pragma unroll
        for (int o = 1; o < 8; o <<= 1) {
            int y = __shfl_up_sync(0xffffffffu, x, o);
            if (lane >= o) x += y;
        }
        if (lane < 8) wt[lane] = x;
    }
    __syncthreads();
    return v + ((w > 0) ? wt[w - 1] : 0);
}

__global__ __launch_bounds__(256) void k_scan() {
    __shared__ int wt[8];
    __shared__ int isLast;
    int i = blockIdx.x * 256 + threadIdx.x;
    int v0 = 0;
    if (i < NN) { v0 = g_cnt[i]; g_cnt[i] = 0; }   // read + restore invariant
    int incl = block_incl_scan(v0, wt);
    if (i <= NN) g_off[i] = incl - v0;             // block-local exclusive
    if (threadIdx.x == 255) g_bsum[blockIdx.x] = incl;
    __threadfence();
    if (threadIdx.x == 0)
        isLast = (atomicAdd(&g_done, 1) == (int)gridDim.x - 1);
    __syncthreads();
    if (isLast) {
        __threadfence();                           // see all g_bsum writes
        int j = threadIdx.x;
        int b0 = (j < SB1) ? g_bsum[j] : 0;
        __syncthreads();
        int binc = block_incl_scan(b0, wt);
        if (j < SB1) g_bsum[j] = binc - b0;        // exclusive block offsets
        if (j == 0) g_done = 0;                    // restore invariant
    }
}

// ---------------------------------------------------------------------------
// K6: scatter into CSR (per-node atomic rank, + g_bsum offset).
// ---------------------------------------------------------------------------
__global__ __launch_bounds__(256) void k_scatter(const int*   __restrict__ node_in,
                                                 const int*   __restrict__ node_out,
                                                 const int*   __restrict__ relation,
                                                 const float* __restrict__ edge_weight) {
    int m = blockIdx.x * 256 + threadIdx.x;
    if (m >= MM) return;
    int ni, no, r; float ew;
    if (m < EE) {
        ni = node_in[m]; no = node_out[m]; r = relation[m]; ew = edge_weight[m];
    } else {
        ni = no = m - EE; r = RP1 - 1; ew = 1.f;
    }
    int pos = g_off[no] + g_bsum[no >> 8] + atomicAdd(&g_cnt2[no], 1);
    uint32_t bi = (uint32_t)r * NN + (uint32_t)ni;
    g_erec[pos] = make_uint2(bi | ((uint32_t)r << 24), __float_as_uint(ew));
}

// ---------------------------------------------------------------------------
// K7: gather-side aggregation, 4 edges per warp-step (R11 body + g_bsum).
//   Restores the g_cnt2 zero-invariant.
// ---------------------------------------------------------------------------
__global__ __launch_bounds__(256) void k_agg(float* __restrict__ out) {
    const int n = blockIdx.x * 8 + (threadIdx.x >> 5);
    if (n >= NN) return;
    const int lane = threadIdx.x & 31;
    const int jj = lane >> 3, dd = lane & 7;

    const int start = g_off[n]     + g_bsum[n >> 8];
    const int end   = g_off[n + 1] + g_bsum[(n + 1) >> 8];
    if (lane == 0) g_cnt2[n] = 0;          // restore zero-invariant

    float acc[8];
    #pragma unroll
    for (int k = 0; k < 8; k++) acc[k] = 0.f;
    float esum = 0.f;

    for (int e = start; e < end; e += 4) {
        const int idx = e + jj;
        uint2 cur = (idx < end) ? g_erec[idx] : make_uint2(0u, 0u);
        const uint32_t bi = cur.x & 0xFFFFFFu;
        const uint32_t r  = cur.x >> 24;

        const uint4 hv = *(const uint4*)(g_hidden + (size_t)bi * 64 + dd * 8);
        const float si = __half2float(g_s[(size_t)bi * 16 + dd]);
        const float so = __half2float(g_s[((size_t)r * NN + n) * 16 + 8 + dd]);

        float w = si + so;
        w = (w > 0.f) ? w : NEG_SLOPE * w;
        const float ee = __expf(w) * __uint_as_float(cur.y);

        const float2 f0 = __half22float2(*(const __half2*)&hv.x);
        const float2 f1 = __half22float2(*(const __half2*)&hv.y);
        const float2 f2 = __half22float2(*(const __half2*)&hv.z);
        const float2 f3 = __half22float2(*(const __half2*)&hv.w);
        acc[0] += ee * f0.x; acc[1] += ee * f0.y;
        acc[2] += ee * f1.x; acc[3] += ee * f1.y;
        acc[4] += ee * f2.x; acc[5] += ee * f2.y;
        acc[6] += ee * f3.x; acc[7] += ee * f3.y;
        esum += ee;
    }

    #pragma unroll
    for (int o = 8; o <= 16; o <<= 1) {
        #pragma unroll
        for (int k = 0; k < 8; k++)
            acc[k] += __shfl_xor_sync(0xffffffffu, acc[k], o);
        esum += __shfl_xor_sync(0xffffffffu, esum, o);
    }

    if (jj == 0) {
        const float inv = 1.f / esum;      // >=1 edge per node (self-loop)
        float4 o0, o1;
        o0.x = fmaxf(acc[0] * inv, 0.f);
        o0.y = fmaxf(acc[1] * inv, 0.f);
        o0.z = fmaxf(acc[2] * inv, 0.f);
        o0.w = fmaxf(acc[3] * inv, 0.f);
        o1.x = fmaxf(acc[4] * inv, 0.f);
        o1.y = fmaxf(acc[5] * inv, 0.f);
        o1.z = fmaxf(acc[6] * inv, 0.f);
        o1.w = fmaxf(acc[7] * inv, 0.f);
        *(float4*)(out + (size_t)n * 64 + dd * 8)     = o0;
        *(float4*)(out + (size_t)n * 64 + dd * 8 + 4) = o1;
    }
}

// ---------------------------------------------------------------------------
extern "C" void kernel_launch(void* const* d_in, const int* in_sizes, int n_in,
                              void* d_out, int out_size) {
    const float* x           = (const float*)d_in[0];
    const float* W_tau       = (const float*)d_in[1];
    const float* query       = (const float*)d_in[2];
    const int*   node_in     = (const int*)  d_in[3];
    const int*   node_out    = (const int*)  d_in[4];
    const int*   relation    = (const int*)  d_in[5];
    const float* edge_weight = (const float*)d_in[6];

    // 1-3: independent front work (separate kernels — fusion regressed)
    k_hist<<<(MM + 255) / 256, 256>>>(node_out);
    k_prepX<<<(G16 * 4 * 32 + 255) / 256, 256>>>(x);
    k_prepWB<<<RP1, 256>>>(W_tau, query);
    // 4: node transform (tensor cores; profiled launch)
    dim3 gg(MT2, 5);
    k_gemm<<<gg, 128>>>(0);
    // 5: one-kernel prefix sum (last-block pattern)
    k_scan<<<SB1, 256>>>();
    // 6: scatter into CSR
    k_scatter<<<(MM + 255) / 256, 256>>>(node_in, node_out, relation, edge_weight);
    // 7: gather-side aggregation
    k_agg<<<(NN + 7) / 8, 256>>>((float*)d_out);
}

// round 16
// speedup vs baseline: 1.7105x; 1.0598x over previous
#include <cuda_runtime.h>
#include <cuda_bf16.h>
#include <cuda_fp16.h>
#include <cstdint>

// Problem constants
#define NN      50000        // nodes
#define EE      800000       // edges
#define MM      (EE + NN)    // edges + self loops
#define HH      8            // heads
#define RP1     9            // relations + 1 (self-loop relation = 8)
#define NEG_SLOPE 0.2f

#define NB      80           // GEMM N: 64 hidden dims + 8 s_in + 8 s_out
#define MT2     391          // ceil(NN / 128)
#define G16     3128         // 391*8 node-groups of 16
#define SB1     196          // ceil(NN / 256) scan blocks
#define SOW     44           // sOut row stride in words (bank-conflict-free)

// ---------------------------------------------------------------------------
// Scratch (device globals; allocation-free per harness rules).
// Zero-init at load; g_cnt / g_cnt2 / g_done re-zeroed every call (invariants).
// ---------------------------------------------------------------------------
__device__ __half         g_hidden[(size_t)RP1 * NN * 64]; // 57.6 MB fp16
__device__ __half         g_s[(size_t)RP1 * NN * 16];      // 14.4 MB fp16
__device__ __half         g_Bh[RP1 * NB * 64];             // B' rows fp16 (K=64)
__device__ uint4          g_xf[(size_t)G16 * 4 * 32];      // A fp16 frag order
__device__ uint4          g_Bf[RP1 * 640];                 // B fp16 frag order
// CSR sort scratch
__device__ int            g_cnt[NN];                       // zero-invariant
__device__ int            g_cnt2[NN];                      // zero-invariant
__device__ int            g_off[NN + 1];                   // block-local exclusive
__device__ int            g_bsum[256];                     // block offsets (excl)
__device__ int            g_done;                          // zero-invariant
__device__ uint2          g_erec[MM];                      // (bi | rel<<24, ew)

// ---------------------------------------------------------------------------
__device__ __forceinline__ void mma_f16(float* c, uint32_t a0, uint32_t a1,
                                        uint32_t a2, uint32_t a3,
                                        uint32_t b0, uint32_t b1) {
    asm volatile(
        "mma.sync.aligned.m16n8k16.row.col.f32.f16.f16.f32 "
        "{%0,%1,%2,%3}, {%4,%5,%6,%7}, {%8,%9}, {%0,%1,%2,%3};"
        : "+f"(c[0]), "+f"(c[1]), "+f"(c[2]), "+f"(c[3])
        : "r"(a0), "r"(a1), "r"(a2), "r"(a3), "r"(b0), "r"(b1));
}
__device__ __forceinline__ uint32_t pack_h2(float a, float b) {
    __half2 p = __floats2half2_rn(a, b);
    return *(uint32_t*)&p;
}

// ---------------------------------------------------------------------------
// K1: histogram of destinations (fire-and-forget REDG atomics, 16 regs).
// ---------------------------------------------------------------------------
__global__ __launch_bounds__(256) void k_hist(const int* __restrict__ node_out) {
    int m = blockIdx.x * 256 + threadIdx.x;
    if (m >= MM) return;
    int no = (m < EE) ? node_out[m] : (m - EE);
    atomicAdd(&g_cnt[no], 1);
}

// ---------------------------------------------------------------------------
// K2: prepX — x -> A-fragment order fp16 (K=64).
// ---------------------------------------------------------------------------
__global__ __launch_bounds__(256) void k_prepX(const float* __restrict__ x) {
    int i = blockIdx.x * 256 + threadIdx.x;
    if (i >= G16 * 4 * 32) return;
    const int lane = i & 31;
    const int cbb  = (i >> 5) & 3;
    const int g16  = i >> 7;
    const int g = lane >> 2, t = lane & 3;
    const int n0 = g16 * 16 + g, n1 = n0 + 8;
    const int c0 = cbb * 16 + 2 * t;

    float2 v00 = {0.f, 0.f}, v01 = {0.f, 0.f}, v10 = {0.f, 0.f}, v11 = {0.f, 0.f};
    if (n0 < NN) {
        v00 = *(const float2*)(x + (size_t)n0 * 64 + c0);
        v01 = *(const float2*)(x + (size_t)n0 * 64 + c0 + 8);
    }
    if (n1 < NN) {
        v10 = *(const float2*)(x + (size_t)n1 * 64 + c0);
        v11 = *(const float2*)(x + (size_t)n1 * 64 + c0 + 8);
    }
    uint4 a;
    a.x = pack_h2(v00.x, v00.y);
    a.y = pack_h2(v10.x, v10.y);
    a.z = pack_h2(v01.x, v01.y);
    a.w = pack_h2(v11.x, v11.y);
    g_xf[((size_t)g16 * 4 + cbb) * 32 + lane] = a;
}

// ---------------------------------------------------------------------------
// K3: prepWB — B' rows fp16, then permute to frag order.
// ---------------------------------------------------------------------------
__global__ __launch_bounds__(256) void k_prepWB(const float* __restrict__ W,
                                                const float* __restrict__ query) {
    const int r = blockIdx.x, tid = threadIdx.x;
    const float* Wr = W + (size_t)r * 64 * 64;

    if (tid < NB) {
        __half* b = g_Bh + ((size_t)r * NB + tid) * 64;
        for (int i = 0; i < 64; i++) {
            float v;
            if (tid < 64) {
                v = Wr[tid * 64 + i];
            } else {
                int h = (tid - 64) & 7;
                int par = (tid - 64) >> 3;
                const float* q = query + ((size_t)r * HH + h) * 16 + par;
                float acc = 0.f;
                #pragma unroll
                for (int j = 0; j < 8; j++) acc += q[2 * j] * Wr[(h * 8 + j) * 64 + i];
                v = acc;
            }
            b[i] = __float2half(v);
        }
    }
    __syncthreads();

    #pragma unroll
    for (int k = 0; k < 3; k++) {
        int f = tid + k * 256;             // 0..639
        if (f < 640) {
            int cb   = f / 160;
            int rem  = f - cb * 160;
            int j    = rem >> 5;
            int lane = rem & 31;
            int g = lane >> 2, t = lane & 3;
            const __half* B0 = g_Bh + ((size_t)r * NB + j * 16 + g) * 64;
            const __half* B1 = B0 + 8 * 64;
            uint4 v;
            v.x = *(const uint32_t*)(B0 + cb * 16 + 2 * t);
            v.y = *(const uint32_t*)(B0 + cb * 16 + 8 + 2 * t);
            v.z = *(const uint32_t*)(B1 + cb * 16 + 2 * t);
            v.w = *(const uint32_t*)(B1 + cb * 16 + 8 + 2 * t);
            g_Bf[r * 640 + f] = v;
        }
    }
}

// ---------------------------------------------------------------------------
// K4: gemm — fp16 mma, K=64, frag-direct A, 2 relations per CTA.
//   Epilogue staged through smem (stride-44 rows: STS banks (12g+t)%32 form a
//   perfect permutation) then written as fully coalesced STG.128.
// ---------------------------------------------------------------------------
__global__ __launch_bounds__(128) void k_gemm(int dummy) {
    __shared__ uint4    sBf[2][640];       // 20 KB
    __shared__ uint32_t sOut[128 * SOW];   // 22.5 KB staging

    const int r0    = blockIdx.y * 2;
    const int nrel  = (r0 + 1 < RP1) ? 2 : 1;
    const int mbase = blockIdx.x * 128;
    const int tid   = threadIdx.x;
    const int w     = tid >> 5, lane = tid & 31;

    for (int p = 0; p < nrel; p++)
        #pragma unroll
        for (int k = 0; k < 5; k++)
            sBf[p][tid + k * 128] = g_Bf[(r0 + p) * 640 + tid + k * 128];

    uint4 af[2][4];
    const int gb = blockIdx.x * 8 + w * 2;
    #pragma unroll
    for (int i = 0; i < 2; i++)
        #pragma unroll
        for (int cb = 0; cb < 4; cb++)
            af[i][cb] = g_xf[((size_t)(gb + i) * 4 + cb) * 32 + lane];

    __syncthreads();

    const int g = lane >> 2, t = lane & 3;
    const int maxn = NN - mbase;

    for (int p = 0; p < nrel; p++) {
        const int r = r0 + p;

        float acc[2][40];
        #pragma unroll
        for (int i = 0; i < 2; i++)
            #pragma unroll
            for (int k = 0; k < 40; k++) acc[i][k] = 0.f;

        #pragma unroll
        for (int cb = 0; cb < 4; cb++) {
            uint4 bf[5];
            #pragma unroll
            for (int j = 0; j < 5; j++) bf[j] = sBf[p][(cb * 5 + j) * 32 + lane];

            #pragma unroll
            for (int i = 0; i < 2; i++)
                #pragma unroll
                for (int nt = 0; nt < 10; nt++) {
                    uint32_t b0 = (nt & 1) ? bf[nt >> 1].z : bf[nt >> 1].x;
                    uint32_t b1 = (nt & 1) ? bf[nt >> 1].w : bf[nt >> 1].y;
                    mma_f16(acc[i] + nt * 4, af[i][cb].x, af[i][cb].y,
                            af[i][cb].z, af[i][cb].w, b0, b1);
                }
        }

        // ---- stage accumulators into sOut (conflict-free STS.32) ----
        #pragma unroll
        for (int i = 0; i < 2; i++)
            #pragma unroll
            for (int half = 0; half < 2; half++) {
                const int node = w * 32 + i * 16 + g + 8 * half;
                uint32_t* row = sOut + node * SOW;
                #pragma unroll
                for (int nt = 0; nt < 10; nt++)
                    row[nt * 4 + t] = pack_h2(acc[i][nt * 4 + 2 * half],
                                              acc[i][nt * 4 + 2 * half + 1]);
            }
        __syncthreads();

        // ---- coalesced stores: hidden (8 uint4/thread), s (2 uint4/thread) ----
        {
            uint4* hdst = (uint4*)(g_hidden + ((size_t)r * NN + mbase) * 64);
            #pragma unroll
            for (int k = 0; k < 8; k++) {
                int u = k * 128 + tid;
                int node = u >> 3, seg = u & 7;
                if (node < maxn)
                    hdst[u] = *(uint4*)(sOut + node * SOW + seg * 4);
            }
            uint4* sdst = (uint4*)(g_s + ((size_t)r * NN + mbase) * 16);
            #pragma unroll
            for (int k = 0; k < 2; k++) {
                int u = k * 128 + tid;
                int node = u >> 1, seg = u & 1;
                if (node < maxn)
                    sdst[u] = *(uint4*)(sOut + node * SOW + 32 + seg * 4);
            }
        }
        if (p + 1 < nrel) __syncthreads();  // sOut reused next relation
    }
}

// ---------------------------------------------------------------------------
// K5: single-kernel prefix sum (last-block pattern).
// ---------------------------------------------------------------------------
__device__ __forceinline__ int block_incl_scan(int v, int* wt) {
    int lane = threadIdx.x & 31, w = threadIdx.x >> 5;
    #pragma unroll
    for (int o = 1; o < 32; o <<= 1) {
        int y = __shfl_up_sync(0xffffffffu, v, o);
        if (lane >= o) v += y;
    }
    if (lane == 31) wt[w] = v;
    __syncthreads();
    if (w == 0) {
        int x = (lane < 8) ? wt[lane] : 0;
        #pragma unroll
        for (int o = 1; o < 8; o <<= 1) {
            int y = __shfl_up_sync(0xffffffffu, x, o);
            if (lane >= o) x += y;
        }
        if (lane < 8) wt[lane] = x;
    }
    __syncthreads();
    return v + ((w > 0) ? wt[w - 1] : 0);
}

__global__ __launch_bounds__(256) void k_scan() {
    __shared__ int wt[8];
    __shared__ int isLast;
    int i = blockIdx.x * 256 + threadIdx.x;
    int v0 = 0;
    if (i < NN) { v0 = g_cnt[i]; g_cnt[i] = 0; }   // read + restore invariant
    int incl = block_incl_scan(v0, wt);
    if (i <= NN) g_off[i] = incl - v0;             // block-local exclusive
    if (threadIdx.x == 255) g_bsum[blockIdx.x] = incl;
    __threadfence();
    if (threadIdx.x == 0)
        isLast = (atomicAdd(&g_done, 1) == (int)gridDim.x - 1);
    __syncthreads();
    if (isLast) {
        __threadfence();
        int j = threadIdx.x;
        int b0 = (j < SB1) ? g_bsum[j] : 0;
        __syncthreads();
        int binc = block_incl_scan(b0, wt);
        if (j < SB1) g_bsum[j] = binc - b0;        // exclusive block offsets
        if (j == 0) g_done = 0;                    // restore invariant
    }
}

// ---------------------------------------------------------------------------
// K6: scatter into CSR (per-node atomic rank, + g_bsum offset).
// ---------------------------------------------------------------------------
__global__ __launch_bounds__(256) void k_scatter(const int*   __restrict__ node_in,
                                                 const int*   __restrict__ node_out,
                                                 const int*   __restrict__ relation,
                                                 const float* __restrict__ edge_weight) {
    int m = blockIdx.x * 256 + threadIdx.x;
    if (m >= MM) return;
    int ni, no, r; float ew;
    if (m < EE) {
        ni = node_in[m]; no = node_out[m]; r = relation[m]; ew = edge_weight[m];
    } else {
        ni = no = m - EE; r = RP1 - 1; ew = 1.f;
    }
    int pos = g_off[no] + g_bsum[no >> 8] + atomicAdd(&g_cnt2[no], 1);
    uint32_t bi = (uint32_t)r * NN + (uint32_t)ni;
    g_erec[pos] = make_uint2(bi | ((uint32_t)r << 24), __float_as_uint(ew));
}

// ---------------------------------------------------------------------------
// K7: gather-side aggregation, 4 edges per warp-step.
//   Restores the g_cnt2 zero-invariant.
// ---------------------------------------------------------------------------
__global__ __launch_bounds__(256) void k_agg(float* __restrict__ out) {
    const int n = blockIdx.x * 8 + (threadIdx.x >> 5);
    if (n >= NN) return;
    const int lane = threadIdx.x & 31;
    const int jj = lane >> 3, dd = lane & 7;

    const int start = g_off[n]     + g_bsum[n >> 8];
    const int end   = g_off[n + 1] + g_bsum[(n + 1) >> 8];
    if (lane == 0) g_cnt2[n] = 0;          // restore zero-invariant

    float acc[8];
    #pragma unroll
    for (int k = 0; k < 8; k++) acc[k] = 0.f;
    float esum = 0.f;

    for (int e = start; e < end; e += 4) {
        const int idx = e + jj;
        uint2 cur = (idx < end) ? g_erec[idx] : make_uint2(0u, 0u);
        const uint32_t bi = cur.x & 0xFFFFFFu;
        const uint32_t r  = cur.x >> 24;

        const uint4 hv = *(const uint4*)(g_hidden + (size_t)bi * 64 + dd * 8);
        const float si = __half2float(g_s[(size_t)bi * 16 + dd]);
        const float so = __half2float(g_s[((size_t)r * NN + n) * 16 + 8 + dd]);

        float w = si + so;
        w = (w > 0.f) ? w : NEG_SLOPE * w;
        const float ee = __expf(w) * __uint_as_float(cur.y);

        const float2 f0 = __half22float2(*(const __half2*)&hv.x);
        const float2 f1 = __half22float2(*(const __half2*)&hv.y);
        const float2 f2 = __half22float2(*(const __half2*)&hv.z);
        const float2 f3 = __half22float2(*(const __half2*)&hv.w);
        acc[0] += ee * f0.x; acc[1] += ee * f0.y;
        acc[2] += ee * f1.x; acc[3] += ee * f1.y;
        acc[4] += ee * f2.x; acc[5] += ee * f2.y;
        acc[6] += ee * f3.x; acc[7] += ee * f3.y;
        esum += ee;
    }

    #pragma unroll
    for (int o = 8; o <= 16; o <<= 1) {
        #pragma unroll
        for (int k = 0; k < 8; k++)
            acc[k] += __shfl_xor_sync(0xffffffffu, acc[k], o);
        esum += __shfl_xor_sync(0xffffffffu, esum, o);
    }

    if (jj == 0) {
        const float inv = 1.f / esum;      // >=1 edge per node (self-loop)
        float4 o0, o1;
        o0.x = fmaxf(acc[0] * inv, 0.f);
        o0.y = fmaxf(acc[1] * inv, 0.f);
        o0.z = fmaxf(acc[2] * inv, 0.f);
        o0.w = fmaxf(acc[3] * inv, 0.f);
        o1.x = fmaxf(acc[4] * inv, 0.f);
        o1.y = fmaxf(acc[5] * inv, 0.f);
        o1.z = fmaxf(acc[6] * inv, 0.f);
        o1.w = fmaxf(acc[7] * inv, 0.f);
        *(float4*)(out + (size_t)n * 64 + dd * 8)     = o0;
        *(float4*)(out + (size_t)n * 64 + dd * 8 + 4) = o1;
    }
}

// ---------------------------------------------------------------------------
extern "C" void kernel_launch(void* const* d_in, const int* in_sizes, int n_in,
                              void* d_out, int out_size) {
    const float* x           = (const float*)d_in[0];
    const float* W_tau       = (const float*)d_in[1];
    const float* query       = (const float*)d_in[2];
    const int*   node_in     = (const int*)  d_in[3];
    const int*   node_out    = (const int*)  d_in[4];
    const int*   relation    = (const int*)  d_in[5];
    const float* edge_weight = (const float*)d_in[6];

    // 1-3: independent front work
    k_hist<<<(MM + 255) / 256, 256>>>(node_out);
    k_prepX<<<(G16 * 4 * 32 + 255) / 256, 256>>>(x);
    k_prepWB<<<RP1, 256>>>(W_tau, query);
    // 4: node transform (tensor cores; profiled launch)
    dim3 gg(MT2, 5);
    k_gemm<<<gg, 128>>>(0);
    // 5: one-kernel prefix sum
    k_scan<<<SB1, 256>>>();
    // 6: scatter into CSR
    k_scatter<<<(MM + 255) / 256, 256>>>(node_in, node_out, relation, edge_weight);
    // 7: gather-side aggregation
    k_agg<<<(NN + 7) / 8, 256>>>((float*)d_out);
}

// round 17
// speedup vs baseline: 1.9016x; 1.1117x over previous
#include <cuda_runtime.h>
#include <cuda_bf16.h>
#include <cuda_fp16.h>
#include <cstdint>

// Problem constants
#define NN      50000        // nodes
#define EE      800000       // edges
#define MM      (EE + NN)    // edges + self loops
#define HH      8            // heads
#define RP1     9            // relations + 1 (self-loop relation = 8)
#define NEG_SLOPE 0.2f

#define NB      80           // GEMM N: 64 hidden dims + 8 s_in + 8 s_out
#define MT2     391          // ceil(NN / 128)
#define G16     3128         // 391*8 node-groups of 16
#define SB1     196          // ceil(NN / 256) scan blocks
#define SOW     44           // sOut row stride in words (bank-conflict-free)

// ---------------------------------------------------------------------------
// Scratch (device globals; allocation-free per harness rules).
// Zero-init at load; g_cnt / g_cnt2 / g_done re-zeroed every call (invariants).
// ---------------------------------------------------------------------------
__device__ __half         g_hidden[(size_t)RP1 * NN * 64]; // 57.6 MB fp16
__device__ __half         g_s[(size_t)RP1 * NN * 16];      // 14.4 MB fp16
__device__ __half         g_Bh[RP1 * NB * 64];             // B' rows fp16 (K=64)
__device__ uint4          g_xf[(size_t)G16 * 4 * 32];      // A fp16 frag order
__device__ uint4          g_Bf[RP1 * 640];                 // B fp16 frag order
// CSR sort scratch
__device__ int            g_cnt[NN];                       // zero-invariant
__device__ int            g_cnt2[NN];                      // zero-invariant
__device__ int            g_off[NN + 1];                   // block-local exclusive
__device__ int            g_bsum[256];                     // block offsets (excl)
__device__ int            g_done;                          // zero-invariant
__device__ uint2          g_erec[MM];                      // (bi | rel<<24, ew)

// ---------------------------------------------------------------------------
__device__ __forceinline__ void mma_f16(float* c, uint32_t a0, uint32_t a1,
                                        uint32_t a2, uint32_t a3,
                                        uint32_t b0, uint32_t b1) {
    asm volatile(
        "mma.sync.aligned.m16n8k16.row.col.f32.f16.f16.f32 "
        "{%0,%1,%2,%3}, {%4,%5,%6,%7}, {%8,%9}, {%0,%1,%2,%3};"
        : "+f"(c[0]), "+f"(c[1]), "+f"(c[2]), "+f"(c[3])
        : "r"(a0), "r"(a1), "r"(a2), "r"(a3), "r"(b0), "r"(b1));
}
__device__ __forceinline__ uint32_t pack_h2(float a, float b) {
    __half2 p = __floats2half2_rn(a, b);
    return *(uint32_t*)&p;
}

// ---------------------------------------------------------------------------
// K1: histogram of destinations (fire-and-forget REDG atomics, 16 regs).
// ---------------------------------------------------------------------------
__global__ __launch_bounds__(256) void k_hist(const int* __restrict__ node_out) {
    int m = blockIdx.x * 256 + threadIdx.x;
    if (m >= MM) return;
    int no = (m < EE) ? node_out[m] : (m - EE);
    atomicAdd(&g_cnt[no], 1);
}

// ---------------------------------------------------------------------------
// K2: prepX — x -> A-fragment order fp16 (K=64).
// ---------------------------------------------------------------------------
__global__ __launch_bounds__(256) void k_prepX(const float* __restrict__ x) {
    int i = blockIdx.x * 256 + threadIdx.x;
    if (i >= G16 * 4 * 32) return;
    const int lane = i & 31;
    const int cbb  = (i >> 5) & 3;
    const int g16  = i >> 7;
    const int g = lane >> 2, t = lane & 3;
    const int n0 = g16 * 16 + g, n1 = n0 + 8;
    const int c0 = cbb * 16 + 2 * t;

    float2 v00 = {0.f, 0.f}, v01 = {0.f, 0.f}, v10 = {0.f, 0.f}, v11 = {0.f, 0.f};
    if (n0 < NN) {
        v00 = *(const float2*)(x + (size_t)n0 * 64 + c0);
        v01 = *(const float2*)(x + (size_t)n0 * 64 + c0 + 8);
    }
    if (n1 < NN) {
        v10 = *(const float2*)(x + (size_t)n1 * 64 + c0);
        v11 = *(const float2*)(x + (size_t)n1 * 64 + c0 + 8);
    }
    uint4 a;
    a.x = pack_h2(v00.x, v00.y);
    a.y = pack_h2(v10.x, v10.y);
    a.z = pack_h2(v01.x, v01.y);
    a.w = pack_h2(v11.x, v11.y);
    g_xf[((size_t)g16 * 4 + cbb) * 32 + lane] = a;
}

// ---------------------------------------------------------------------------
// K3: prepWB — B' rows fp16, then permute to frag order.
// ---------------------------------------------------------------------------
__global__ __launch_bounds__(256) void k_prepWB(const float* __restrict__ W,
                                                const float* __restrict__ query) {
    const int r = blockIdx.x, tid = threadIdx.x;
    const float* Wr = W + (size_t)r * 64 * 64;

    if (tid < NB) {
        __half* b = g_Bh + ((size_t)r * NB + tid) * 64;
        for (int i = 0; i < 64; i++) {
            float v;
            if (tid < 64) {
                v = Wr[tid * 64 + i];
            } else {
                int h = (tid - 64) & 7;
                int par = (tid - 64) >> 3;
                const float* q = query + ((size_t)r * HH + h) * 16 + par;
                float acc = 0.f;
                #pragma unroll
                for (int j = 0; j < 8; j++) acc += q[2 * j] * Wr[(h * 8 + j) * 64 + i];
                v = acc;
            }
            b[i] = __float2half(v);
        }
    }
    __syncthreads();

    #pragma unroll
    for (int k = 0; k < 3; k++) {
        int f = tid + k * 256;             // 0..639
        if (f < 640) {
            int cb   = f / 160;
            int rem  = f - cb * 160;
            int j    = rem >> 5;
            int lane = rem & 31;
            int g = lane >> 2, t = lane & 3;
            const __half* B0 = g_Bh + ((size_t)r * NB + j * 16 + g) * 64;
            const __half* B1 = B0 + 8 * 64;
            uint4 v;
            v.x = *(const uint32_t*)(B0 + cb * 16 + 2 * t);
            v.y = *(const uint32_t*)(B0 + cb * 16 + 8 + 2 * t);
            v.z = *(const uint32_t*)(B1 + cb * 16 + 2 * t);
            v.w = *(const uint32_t*)(B1 + cb * 16 + 8 + 2 * t);
            g_Bf[r * 640 + f] = v;
        }
    }
}

// ---------------------------------------------------------------------------
// K4: gemm — fp16 mma, K=64, frag-direct A, 2 relations per CTA.
//   Epilogue staged through smem (stride-44 rows) -> coalesced STG.128.
// ---------------------------------------------------------------------------
__global__ __launch_bounds__(128) void k_gemm(int dummy) {
    __shared__ uint4    sBf[2][640];       // 20 KB
    __shared__ uint32_t sOut[128 * SOW];   // 22.5 KB staging

    const int r0    = blockIdx.y * 2;
    const int nrel  = (r0 + 1 < RP1) ? 2 : 1;
    const int mbase = blockIdx.x * 128;
    const int tid   = threadIdx.x;
    const int w     = tid >> 5, lane = tid & 31;

    for (int p = 0; p < nrel; p++)
        #pragma unroll
        for (int k = 0; k < 5; k++)
            sBf[p][tid + k * 128] = g_Bf[(r0 + p) * 640 + tid + k * 128];

    uint4 af[2][4];
    const int gb = blockIdx.x * 8 + w * 2;
    #pragma unroll
    for (int i = 0; i < 2; i++)
        #pragma unroll
        for (int cb = 0; cb < 4; cb++)
            af[i][cb] = g_xf[((size_t)(gb + i) * 4 + cb) * 32 + lane];

    __syncthreads();

    const int g = lane >> 2, t = lane & 3;
    const int maxn = NN - mbase;

    for (int p = 0; p < nrel; p++) {
        const int r = r0 + p;

        float acc[2][40];
        #pragma unroll
        for (int i = 0; i < 2; i++)
            #pragma unroll
            for (int k = 0; k < 40; k++) acc[i][k] = 0.f;

        #pragma unroll
        for (int cb = 0; cb < 4; cb++) {
            uint4 bf[5];
            #pragma unroll
            for (int j = 0; j < 5; j++) bf[j] = sBf[p][(cb * 5 + j) * 32 + lane];

            #pragma unroll
            for (int i = 0; i < 2; i++)
                #pragma unroll
                for (int nt = 0; nt < 10; nt++) {
                    uint32_t b0 = (nt & 1) ? bf[nt >> 1].z : bf[nt >> 1].x;
                    uint32_t b1 = (nt & 1) ? bf[nt >> 1].w : bf[nt >> 1].y;
                    mma_f16(acc[i] + nt * 4, af[i][cb].x, af[i][cb].y,
                            af[i][cb].z, af[i][cb].w, b0, b1);
                }
        }

        // ---- stage accumulators into sOut (conflict-free STS.32) ----
        #pragma unroll
        for (int i = 0; i < 2; i++)
            #pragma unroll
            for (int half = 0; half < 2; half++) {
                const int node = w * 32 + i * 16 + g + 8 * half;
                uint32_t* row = sOut + node * SOW;
                #pragma unroll
                for (int nt = 0; nt < 10; nt++)
                    row[nt * 4 + t] = pack_h2(acc[i][nt * 4 + 2 * half],
                                              acc[i][nt * 4 + 2 * half + 1]);
            }
        __syncthreads();

        // ---- coalesced stores: hidden (8 uint4/thread), s (2 uint4/thread) ----
        {
            uint4* hdst = (uint4*)(g_hidden + ((size_t)r * NN + mbase) * 64);
            #pragma unroll
            for (int k = 0; k < 8; k++) {
                int u = k * 128 + tid;
                int node = u >> 3, seg = u & 7;
                if (node < maxn)
                    hdst[u] = *(uint4*)(sOut + node * SOW + seg * 4);
            }
            uint4* sdst = (uint4*)(g_s + ((size_t)r * NN + mbase) * 16);
            #pragma unroll
            for (int k = 0; k < 2; k++) {
                int u = k * 128 + tid;
                int node = u >> 1, seg = u & 1;
                if (node < maxn)
                    sdst[u] = *(uint4*)(sOut + node * SOW + 32 + seg * 4);
            }
        }
        if (p + 1 < nrel) __syncthreads();  // sOut reused next relation
    }
}

// ---------------------------------------------------------------------------
// K5: single-kernel prefix sum (last-block pattern).
// ---------------------------------------------------------------------------
__device__ __forceinline__ int block_incl_scan(int v, int* wt) {
    int lane = threadIdx.x & 31, w = threadIdx.x >> 5;
    #pragma unroll
    for (int o = 1; o < 32; o <<= 1) {
        int y = __shfl_up_sync(0xffffffffu, v, o);
        if (lane >= o) v += y;
    }
    if (lane == 31) wt[w] = v;
    __syncthreads();
    if (w == 0) {
        int x = (lane < 8) ? wt[lane] : 0;
        #pragma unroll
        for (int o = 1; o < 8; o <<= 1) {
            int y = __shfl_up_sync(0xffffffffu, x, o);
            if (lane >= o) x += y;
        }
        if (lane < 8) wt[lane] = x;
    }
    __syncthreads();
    return v + ((w > 0) ? wt[w - 1] : 0);
}

__global__ __launch_bounds__(256) void k_scan() {
    __shared__ int wt[8];
    __shared__ int isLast;
    int i = blockIdx.x * 256 + threadIdx.x;
    int v0 = 0;
    if (i < NN) { v0 = g_cnt[i]; g_cnt[i] = 0; }   // read + restore invariant
    int incl = block_incl_scan(v0, wt);
    if (i <= NN) g_off[i] = incl - v0;             // block-local exclusive
    if (threadIdx.x == 255) g_bsum[blockIdx.x] = incl;
    __threadfence();
    if (threadIdx.x == 0)
        isLast = (atomicAdd(&g_done, 1) == (int)gridDim.x - 1);
    __syncthreads();
    if (isLast) {
        __threadfence();
        int j = threadIdx.x;
        int b0 = (j < SB1) ? g_bsum[j] : 0;
        __syncthreads();
        int binc = block_incl_scan(b0, wt);
        if (j < SB1) g_bsum[j] = binc - b0;        // exclusive block offsets
        if (j == 0) g_done = 0;                    // restore invariant
    }
}

// ---------------------------------------------------------------------------
// K6: scatter into CSR (per-node atomic rank, + g_bsum offset).
// ---------------------------------------------------------------------------
__global__ __launch_bounds__(256) void k_scatter(const int*   __restrict__ node_in,
                                                 const int*   __restrict__ node_out,
                                                 const int*   __restrict__ relation,
                                                 const float* __restrict__ edge_weight) {
    int m = blockIdx.x * 256 + threadIdx.x;
    if (m >= MM) return;
    int ni, no, r; float ew;
    if (m < EE) {
        ni = node_in[m]; no = node_out[m]; r = relation[m]; ew = edge_weight[m];
    } else {
        ni = no = m - EE; r = RP1 - 1; ew = 1.f;
    }
    int pos = g_off[no] + g_bsum[no >> 8] + atomicAdd(&g_cnt2[no], 1);
    uint32_t bi = (uint32_t)r * NN + (uint32_t)ni;
    g_erec[pos] = make_uint2(bi | ((uint32_t)r << 24), __float_as_uint(ew));
}

// ---------------------------------------------------------------------------
// K7: gather-side aggregation, 4 edges per warp-step.
//   Restores the g_cnt2 zero-invariant.
// ---------------------------------------------------------------------------
__global__ __launch_bounds__(256) void k_agg(float* __restrict__ out) {
    const int n = blockIdx.x * 8 + (threadIdx.x >> 5);
    if (n >= NN) return;
    const int lane = threadIdx.x & 31;
    const int jj = lane >> 3, dd = lane & 7;

    const int start = g_off[n]     + g_bsum[n >> 8];
    const int end   = g_off[n + 1] + g_bsum[(n + 1) >> 8];
    if (lane == 0) g_cnt2[n] = 0;          // restore zero-invariant

    float acc[8];
    #pragma unroll
    for (int k = 0; k < 8; k++) acc[k] = 0.f;
    float esum = 0.f;

    for (int e = start; e < end; e += 4) {
        const int idx = e + jj;
        uint2 cur = (idx < end) ? g_erec[idx] : make_uint2(0u, 0u);
        const uint32_t bi = cur.x & 0xFFFFFFu;
        const uint32_t r  = cur.x >> 24;

        const uint4 hv = *(const uint4*)(g_hidden + (size_t)bi * 64 + dd * 8);
        const float si = __half2float(g_s[(size_t)bi * 16 + dd]);
        const float so = __half2float(g_s[((size_t)r * NN + n) * 16 + 8 + dd]);

        float w = si + so;
        w = (w > 0.f) ? w : NEG_SLOPE * w;
        const float ee = __expf(w) * __uint_as_float(cur.y);

        const float2 f0 = __half22float2(*(const __half2*)&hv.x);
        const float2 f1 = __half22float2(*(const __half2*)&hv.y);
        const float2 f2 = __half22float2(*(const __half2*)&hv.z);
        const float2 f3 = __half22float2(*(const __half2*)&hv.w);
        acc[0] += ee * f0.x; acc[1] += ee * f0.y;
        acc[2] += ee * f1.x; acc[3] += ee * f1.y;
        acc[4] += ee * f2.x; acc[5] += ee * f2.y;
        acc[6] += ee * f3.x; acc[7] += ee * f3.y;
        esum += ee;
    }

    #pragma unroll
    for (int o = 8; o <= 16; o <<= 1) {
        #pragma unroll
        for (int k = 0; k < 8; k++)
            acc[k] += __shfl_xor_sync(0xffffffffu, acc[k], o);
        esum += __shfl_xor_sync(0xffffffffu, esum, o);
    }

    if (jj == 0) {
        const float inv = 1.f / esum;      // >=1 edge per node (self-loop)
        float4 o0, o1;
        o0.x = fmaxf(acc[0] * inv, 0.f);
        o0.y = fmaxf(acc[1] * inv, 0.f);
        o0.z = fmaxf(acc[2] * inv, 0.f);
        o0.w = fmaxf(acc[3] * inv, 0.f);
        o1.x = fmaxf(acc[4] * inv, 0.f);
        o1.y = fmaxf(acc[5] * inv, 0.f);
        o1.z = fmaxf(acc[6] * inv, 0.f);
        o1.w = fmaxf(acc[7] * inv, 0.f);
        *(float4*)(out + (size_t)n * 64 + dd * 8)     = o0;
        *(float4*)(out + (size_t)n * 64 + dd * 8 + 4) = o1;
    }
}

// ---------------------------------------------------------------------------
// Launch: two independent chains forked onto a side stream during capture
// (event fork/join records parallel graph branches), joined before k_agg.
//   main stream: prepX -> prepWB -> gemm        (~28 us)
//   side stream: hist -> scan -> scatter        (~24 us, hides under main)
// ---------------------------------------------------------------------------
extern "C" void kernel_launch(void* const* d_in, const int* in_sizes, int n_in,
                              void* d_out, int out_size) {
    const float* x           = (const float*)d_in[0];
    const float* W_tau       = (const float*)d_in[1];
    const float* query       = (const float*)d_in[2];
    const int*   node_in     = (const int*)  d_in[3];
    const int*   node_out    = (const int*)  d_in[4];
    const int*   relation    = (const int*)  d_in[5];
    const float* edge_weight = (const float*)d_in[6];

    cudaStream_t s1;
    cudaStreamCreateWithFlags(&s1, cudaStreamNonBlocking);
    cudaEvent_t evFork, evJoin;
    cudaEventCreateWithFlags(&evFork, cudaEventDisableTiming);
    cudaEventCreateWithFlags(&evJoin, cudaEventDisableTiming);

    // fork side stream off the capture (default) stream
    cudaEventRecord(evFork, 0);
    cudaStreamWaitEvent(s1, evFork, 0);

    // side: edge chain
    k_hist<<<(MM + 255) / 256, 256, 0, s1>>>(node_out);
    k_scan<<<SB1, 256, 0, s1>>>();
    k_scatter<<<(MM + 255) / 256, 256, 0, s1>>>(node_in, node_out, relation, edge_weight);
    cudaEventRecord(evJoin, s1);

    // main: compute chain
    k_prepX<<<(G16 * 4 * 32 + 255) / 256, 256>>>(x);
    k_prepWB<<<RP1, 256>>>(W_tau, query);
    dim3 gg(MT2, 5);
    k_gemm<<<gg, 128>>>(0);

    // join, then aggregate
    cudaStreamWaitEvent(0, evJoin, 0);
    k_agg<<<(NN + 7) / 8, 256>>>((float*)d_out);
    // NOTE: stream/events intentionally not destroyed — destroying a stream
    // that participates in an active capture invalidates the capture. Host
    // code runs only a handful of times (graph replays skip it).
}